// round 1
// baseline (speedup 1.0000x reference)
#include <cuda_runtime.h>
#include <cstdint>

#define Bx 1024
#define Tx 512
#define Kx 64

// Scratch: backpointers (u8) and viterbi start tag per batch.
__device__ unsigned char g_bp[(long)Bx * Tx * Kx];
__device__ int g_last[Bx];

#define NEG_INF __int_as_float(0xff800000)

__global__ __launch_bounds__(Kx) void crf_forward(
    const float* __restrict__ em, const int* __restrict__ tags,
    const int* __restrict__ mask, const float* __restrict__ trans,
    const float* __restrict__ startt, const float* __restrict__ endt,
    float* __restrict__ out)
{
    __shared__ float2 TE[Kx * Kx];   // (.x = trans[i][j], .y = exp(trans[i][j]))
    __shared__ float2 AV[Kx];        // (.x = a_i = exp(alpha_i - m), .y = v_i)
    __shared__ float  red[Kx];
    __shared__ float  m_sm;
    __shared__ int    tags_sm[Tx];
    __shared__ int    mask_sm[Tx];
    __shared__ float  gw[2];

    const int b = blockIdx.x;
    const int j = threadIdx.x;

    // Load transitions + exp(transitions) into smem (row i major: lane j reads TE[i*K+j])
    for (int idx = j; idx < Kx * Kx; idx += Kx) {
        float tv = trans[idx];
        TE[idx] = make_float2(tv, __expf(tv));
    }
    for (int t = j; t < Tx; t += Kx) {
        tags_sm[t] = tags[(long)b * Tx + t];
        mask_sm[t] = mask[(long)b * Tx + t];
    }

    const float endj = endt[j];
    const float em0  = em[((long)b * Tx) * Kx + j];
    float alpha = startt[j] + em0;   // identical fp ops to reference
    float v     = alpha;

    __syncthreads();

    float gold = 0.f;
    {
        int tg0 = tags_sm[0];
        if (j == tg0) {
            gold += startt[j];
            if (mask_sm[0]) gold += em0;
        }
    }

    const float* emrow  = em + ((long)b * Tx) * Kx + j;
    unsigned char* bprow = g_bp + ((long)b * Tx) * Kx + j;

    for (int t = 1; t < Tx; ++t) {
        // Prefetch emission early (consumed ~end of step)
        const float emv = __ldg(emrow + t * Kx);

        // ---- m = max_j alpha_j (block reduce) ----
        red[j] = alpha;
        __syncthreads();
        if (j < 32) {
            float m = fmaxf(red[j], red[j + 32]);
            #pragma unroll
            for (int o = 16; o; o >>= 1)
                m = fmaxf(m, __shfl_xor_sync(0xffffffffu, m, o));
            if (j == 0) m_sm = m;
        }
        __syncthreads();
        const float m = m_sm;

        const float a = __expf(alpha - m);
        AV[j] = make_float2(a, v);
        __syncthreads();

        // ---- inner K-loop: logZ matvec (FFMA) + viterbi max-plus with exact argmax ----
        float acc0 = 0.f, acc1 = 0.f;
        float b0 = NEG_INF, b1 = NEG_INF, b2 = NEG_INF, b3 = NEG_INF;
        int   a0 = 0, a1 = 16, a2 = 32, a3 = 48;
        #pragma unroll
        for (int i = 0; i < 16; ++i) {
            {   float2 av = AV[i];
                float2 te = TE[i * Kx + j];
                acc0 += av.x * te.y;
                float x = av.y + te.x;
                if (x > b0) { b0 = x; a0 = i; }
            }
            {   float2 av = AV[i + 16];
                float2 te = TE[(i + 16) * Kx + j];
                acc1 += av.x * te.y;
                float x = av.y + te.x;
                if (x > b1) { b1 = x; a1 = i + 16; }
            }
            {   float2 av = AV[i + 32];
                float2 te = TE[(i + 32) * Kx + j];
                acc0 += av.x * te.y;
                float x = av.y + te.x;
                if (x > b2) { b2 = x; a2 = i + 32; }
            }
            {   float2 av = AV[i + 48];
                float2 te = TE[(i + 48) * Kx + j];
                acc1 += av.x * te.y;
                float x = av.y + te.x;
                if (x > b3) { b3 = x; a3 = i + 48; }
            }
        }
        // Combine chains in ascending-i-range order; strict > keeps first max (jnp.argmax ties)
        float best = b0; int arg = a0;
        if (b1 > best) { best = b1; arg = a1; }
        if (b2 > best) { best = b2; arg = a2; }
        if (b3 > best) { best = b3; arg = a3; }

        const float alpha_c = m + __logf(acc0 + acc1) + emv;
        const float v_c     = best + emv;

        const int mt = mask_sm[t];
        if (mt) { alpha = alpha_c; v = v_c; } else { arg = j; }
        bprow[(long)t * Kx] = (unsigned char)arg;

        if (mt && j == tags_sm[t])
            gold += emv + TE[tags_sm[t - 1] * Kx + j].x;
    }

    // ---- final logZ = logsumexp(alpha + end) ----
    red[j] = alpha + endj;
    __syncthreads();
    float logZ = 0.f;
    if (j < 32) {
        float x1 = red[j], x2 = red[j + 32];
        float mm = fmaxf(x1, x2);
        #pragma unroll
        for (int o = 16; o; o >>= 1)
            mm = fmaxf(mm, __shfl_xor_sync(0xffffffffu, mm, o));
        float s = __expf(x1 - mm) + __expf(x2 - mm);
        #pragma unroll
        for (int o = 16; o; o >>= 1)
            s += __shfl_xor_sync(0xffffffffu, s, o);
        logZ = mm + __logf(s);
    }
    __syncthreads();

    // ---- viterbi start tag: argmax(v + end), first-index tie-break ----
    red[j] = v + endj;
    __syncthreads();
    if (j == 0) {
        float bb = red[0]; int aa = 0;
        #pragma unroll 8
        for (int i = 1; i < Kx; ++i) {
            float x = red[i];
            if (x > bb) { bb = x; aa = i; }
        }
        g_last[b] = aa;
    }

    // ---- gold score reduce (sum over threads) ----
    float g = gold;
    #pragma unroll
    for (int o = 16; o; o >>= 1)
        g += __shfl_xor_sync(0xffffffffu, g, o);
    if ((j & 31) == 0) gw[j >> 5] = g;
    __syncthreads();
    if (j == 0) {
        float goldt = gw[0] + gw[1];
        int cnt = 0;
        for (int t = 0; t < Tx; ++t) cnt += (mask_sm[t] != 0);
        int li = cnt - 1;
        goldt += endt[tags_sm[li]];
        out[b] = logZ - goldt;
    }
}

__global__ __launch_bounds__(256) void crf_backtrace(float* __restrict__ out)
{
    __shared__ unsigned char bp_s[Tx * Kx];   // 32 KB
    __shared__ int path_s[Tx];

    const int b = blockIdx.x;
    const int tid = threadIdx.x;

    const int4* src = (const int4*)(g_bp + (long)b * Tx * Kx);
    int4* dst = (int4*)bp_s;
    #pragma unroll
    for (int idx = tid; idx < Tx * Kx / 16; idx += 256) dst[idx] = src[idx];
    __syncthreads();

    if (tid == 0) {
        int cur = g_last[b];
        path_s[Tx - 1] = cur;
        for (int t = Tx - 1; t >= 1; --t) {
            cur = bp_s[t * Kx + cur];
            path_s[t - 1] = cur;
        }
    }
    __syncthreads();

    for (int t = tid; t < Tx; t += 256)
        out[Bx + (long)b * Tx + t] = (float)path_s[t];
}

extern "C" void kernel_launch(void* const* d_in, const int* in_sizes, int n_in,
                              void* d_out, int out_size)
{
    const float* em     = (const float*)d_in[0];
    const int*   tags   = (const int*)d_in[1];
    const int*   mask   = (const int*)d_in[2];
    const float* trans  = (const float*)d_in[3];
    const float* startt = (const float*)d_in[4];
    const float* endt   = (const float*)d_in[5];
    float* out = (float*)d_out;

    crf_forward<<<Bx, Kx>>>(em, tags, mask, trans, startt, endt, out);
    crf_backtrace<<<Bx, 256>>>(out);
}

// round 2
// speedup vs baseline: 1.0667x; 1.0667x over previous
#include <cuda_runtime.h>
#include <cuda_bf16.h>
#include <cstdint>

#define Bx 1024
#define Tx 512
#define Kx 64
#define WPB 7           // warps (batches) per block
#define GRID ((Bx + WPB - 1) / WPB)   // 147

__device__ unsigned char g_bp[(long)Bx * Tx * Kx];
__device__ int g_last[Bx];

#define NEG_INF __int_as_float(0xff800000)

__global__ __launch_bounds__(WPB * 32) void crf_forward(
    const float* __restrict__ em, const int* __restrict__ mask,
    const float* __restrict__ trans, const float* __restrict__ startt,
    const float* __restrict__ endt, float* __restrict__ out)
{
    // Tpk[i*32+l] = (trans[i][l], trans[i][l+32])  f32 exact (viterbi)
    // Epk[i*32+l] = bf16x2(exp(trans[i][l]), exp(trans[i][l+32]))  (logZ)
    __shared__ float2 Tpk[Kx * 32];
    __shared__ unsigned int Epk[Kx * 32];
    __shared__ __align__(16) float2 AVf2[WPB][Kx];   // (a_i, v_i)
    __shared__ unsigned char maskb[WPB][Tx];

    const int tid = threadIdx.x;
    const int w = tid >> 5;
    const int l = tid & 31;
    const int b = blockIdx.x * WPB + w;
    const bool active = (b < Bx);

    // Stage transitions (block-wide)
    for (int idx = tid; idx < Kx * 32; idx += WPB * 32) {
        int i = idx >> 5, c = idx & 31;
        float t0 = trans[i * Kx + c];
        float t1 = trans[i * Kx + c + 32];
        Tpk[idx] = make_float2(t0, t1);
        __nv_bfloat162 h = __float22bfloat162_rn(make_float2(__expf(t0), __expf(t1)));
        Epk[idx] = *reinterpret_cast<unsigned int*>(&h);   // low16 = bf16(e0)
    }
    if (active) {
        for (int t = l; t < Tx; t += 32)
            maskb[w][t] = (unsigned char)(mask[b * Tx + t] != 0);
    }
    __syncthreads();
    if (!active) return;

    const float* emp = em + (long)b * Tx * Kx;
    unsigned char* bpp = g_bp + (long)b * Tx * Kx;

    float alpha0 = startt[l] + emp[l];
    float alpha1 = startt[l + 32] + emp[l + 32];
    float v0 = alpha0, v1 = alpha1;

    for (int t = 1; t < Tx; ++t) {
        // prefetch emissions for this step (consumed at the end)
        const float e0 = __ldg(emp + t * Kx + l);
        const float e1 = __ldg(emp + t * Kx + l + 32);
        const int mt = maskb[w][t];

        // m = max over 64 alphas via warp shuffles (no barriers)
        float m = fmaxf(alpha0, alpha1);
        #pragma unroll
        for (int o = 16; o; o >>= 1)
            m = fmaxf(m, __shfl_xor_sync(0xffffffffu, m, o));

        const float a0 = __expf(alpha0 - m);
        const float a1 = __expf(alpha1 - m);
        AVf2[w][l]      = make_float2(a0, v0);
        AVf2[w][l + 32] = make_float2(a1, v1);
        __syncwarp();

        // logZ accumulators (2 chains per state) + viterbi argmax
        // chain A: i in [0,32) ascending; chain B: i in [32,64) ascending.
        float accA0 = 0.f, accB0 = 0.f, accA1 = 0.f, accB1 = 0.f;
        float bA0 = NEG_INF, bB0 = NEG_INF, bA1 = NEG_INF, bB1 = NEG_INF;
        int   aA0 = 0, aB0 = 32, aA1 = 0, aB1 = 32;

        #pragma unroll
        for (int ii = 0; ii < 16; ++ii) {
            const int iA = 2 * ii;
            const int iB = 32 + 2 * ii;
            const float4 qa = *(const float4*)(&AVf2[w][iA]); // aA,vA,aA1,vA1
            const float4 qb = *(const float4*)(&AVf2[w][iB]);

            {   // i = iA
                float2 tp = Tpk[iA * 32 + l];
                unsigned int ep = Epk[iA * 32 + l];
                float ef0 = __uint_as_float(ep << 16);
                float ef1 = __uint_as_float(ep & 0xffff0000u);
                accA0 += qa.x * ef0;  accA1 += qa.x * ef1;
                float x0 = qa.y + tp.x, x1 = qa.y + tp.y;
                if (x0 > bA0) { bA0 = x0; aA0 = iA; }
                if (x1 > bA1) { bA1 = x1; aA1 = iA; }
            }
            {   // i = iA+1
                float2 tp = Tpk[(iA + 1) * 32 + l];
                unsigned int ep = Epk[(iA + 1) * 32 + l];
                float ef0 = __uint_as_float(ep << 16);
                float ef1 = __uint_as_float(ep & 0xffff0000u);
                accA0 += qa.z * ef0;  accA1 += qa.z * ef1;
                float x0 = qa.w + tp.x, x1 = qa.w + tp.y;
                if (x0 > bA0) { bA0 = x0; aA0 = iA + 1; }
                if (x1 > bA1) { bA1 = x1; aA1 = iA + 1; }
            }
            {   // i = iB
                float2 tp = Tpk[iB * 32 + l];
                unsigned int ep = Epk[iB * 32 + l];
                float ef0 = __uint_as_float(ep << 16);
                float ef1 = __uint_as_float(ep & 0xffff0000u);
                accB0 += qb.x * ef0;  accB1 += qb.x * ef1;
                float x0 = qb.y + tp.x, x1 = qb.y + tp.y;
                if (x0 > bB0) { bB0 = x0; aB0 = iB; }
                if (x1 > bB1) { bB1 = x1; aB1 = iB; }
            }
            {   // i = iB+1
                float2 tp = Tpk[(iB + 1) * 32 + l];
                unsigned int ep = Epk[(iB + 1) * 32 + l];
                float ef0 = __uint_as_float(ep << 16);
                float ef1 = __uint_as_float(ep & 0xffff0000u);
                accB0 += qb.z * ef0;  accB1 += qb.z * ef1;
                float x0 = qb.w + tp.x, x1 = qb.w + tp.y;
                if (x0 > bB0) { bB0 = x0; aB0 = iB + 1; }
                if (x1 > bB1) { bB1 = x1; aB1 = iB + 1; }
            }
        }

        // combine chains in ascending range order; strict > keeps first index
        float best0 = bA0; int arg0 = aA0;
        if (bB0 > best0) { best0 = bB0; arg0 = aB0; }
        float best1 = bA1; int arg1 = aA1;
        if (bB1 > best1) { best1 = bB1; arg1 = aB1; }

        const float na0 = m + __logf(accA0 + accB0) + e0;
        const float na1 = m + __logf(accA1 + accB1) + e1;
        const float nv0 = best0 + e0;
        const float nv1 = best1 + e1;

        if (mt) { alpha0 = na0; alpha1 = na1; v0 = nv0; v1 = nv1; }
        else    { arg0 = l; arg1 = l + 32; }

        bpp[t * Kx + l]      = (unsigned char)arg0;
        bpp[t * Kx + l + 32] = (unsigned char)arg1;
    }

    // ---- logZ = logsumexp(alpha + end) over 64 ----
    const float x0 = alpha0 + endt[l];
    const float x1 = alpha1 + endt[l + 32];
    float mm = fmaxf(x0, x1);
    #pragma unroll
    for (int o = 16; o; o >>= 1)
        mm = fmaxf(mm, __shfl_xor_sync(0xffffffffu, mm, o));
    float s = __expf(x0 - mm) + __expf(x1 - mm);
    #pragma unroll
    for (int o = 16; o; o >>= 1)
        s += __shfl_xor_sync(0xffffffffu, s, o);
    const float logZ = mm + __logf(s);

    // ---- last tag: argmax(v + end) with first-index tie-break ----
    AVf2[w][l].x      = v0 + endt[l];
    AVf2[w][l + 32].x = v1 + endt[l + 32];
    __syncwarp();
    if (l == 0) {
        float bb = AVf2[w][0].x; int aa = 0;
        for (int i = 1; i < Kx; ++i) {
            float x = AVf2[w][i].x;
            if (x > bb) { bb = x; aa = i; }
        }
        g_last[b] = aa;
        out[b] = logZ;   // gold subtracted in backtrace kernel
    }
}

__global__ __launch_bounds__(256) void crf_backtrace(
    const float* __restrict__ em, const int* __restrict__ tags,
    const int* __restrict__ mask, const float* __restrict__ trans,
    const float* __restrict__ startt, const float* __restrict__ endt,
    float* __restrict__ out)
{
    __shared__ unsigned char bp_s[Tx * Kx];   // 32 KB
    __shared__ int path_s[Tx];
    __shared__ float s_gold;
    __shared__ int s_cnt;

    const int b = blockIdx.x;
    const int tid = threadIdx.x;

    if (tid == 0) { s_gold = 0.f; s_cnt = 0; }
    __syncthreads();

    // stage backpointers
    const int4* src = (const int4*)(g_bp + (long)b * Tx * Kx);
    int4* dst = (int4*)bp_s;
    #pragma unroll
    for (int idx = tid; idx < Tx * Kx / 16; idx += 256) dst[idx] = src[idx];

    // gold-score partials
    float gp = 0.f; int cnt = 0;
    for (int t = tid; t < Tx; t += 256) {
        int mk = mask[b * Tx + t];
        float mf = (float)mk;
        cnt += (mk != 0);
        int tg = tags[b * Tx + t];
        gp += em[((long)b * Tx + t) * Kx + tg] * mf;
        if (t > 0) {
            int tgp = tags[b * Tx + t - 1];
            gp += trans[tgp * Kx + tg] * mf;
        }
    }
    atomicAdd(&s_gold, gp);
    atomicAdd(&s_cnt, cnt);
    __syncthreads();

    if (tid == 0) {
        int tg0 = tags[b * Tx];
        int last = s_cnt - 1;
        int tgl = tags[b * Tx + last];
        float gold = s_gold + startt[tg0] + endt[tgl];
        out[b] = out[b] - gold;   // nll = logZ - gold

        int cur = g_last[b];
        path_s[Tx - 1] = cur;
        for (int t = Tx - 1; t >= 1; --t) {
            cur = bp_s[t * Kx + cur];
            path_s[t - 1] = cur;
        }
    }
    __syncthreads();

    for (int t = tid; t < Tx; t += 256)
        out[Bx + (long)b * Tx + t] = (float)path_s[t];
}

extern "C" void kernel_launch(void* const* d_in, const int* in_sizes, int n_in,
                              void* d_out, int out_size)
{
    const float* em     = (const float*)d_in[0];
    const int*   tags   = (const int*)d_in[1];
    const int*   mask   = (const int*)d_in[2];
    const float* trans  = (const float*)d_in[3];
    const float* startt = (const float*)d_in[4];
    const float* endt   = (const float*)d_in[5];
    float* out = (float*)d_out;

    crf_forward<<<GRID, WPB * 32>>>(em, mask, trans, startt, endt, out);
    crf_backtrace<<<Bx, 256>>>(em, tags, mask, trans, startt, endt, out);
}

// round 3
// speedup vs baseline: 1.4626x; 1.3711x over previous
#include <cuda_runtime.h>
#include <cuda_bf16.h>
#include <cstdint>

#define Bx 1024
#define Tx 512
#define Kx 64
#define WPB 7
#define GRID ((Bx + WPB - 1) / WPB)   // 147

// v rows: g_v[(b*511 + t)*32 + l] = (v_t[l], v_t[l+32]), t = 0..510
__device__ float2 g_v[(long)Bx * 511 * 32];
__device__ int g_last[Bx];

#define NEG_INF __int_as_float(0xff800000)

__global__ __launch_bounds__(WPB * 32, 1) void crf_forward(
    const float* __restrict__ em, const int* __restrict__ mask,
    const float* __restrict__ trans, const float* __restrict__ startt,
    const float* __restrict__ endt, float* __restrict__ out)
{
    // smem: i in [32,64) only (i in [0,32) lives in registers)
    __shared__ float2 Tsm[32 * 32];          // Tsm[(i-32)*32+l] = (T[i][l], T[i][l+32])
    __shared__ unsigned int Esm[32 * 32];    // bf16x2(exp(T[i][l]), exp(T[i][l+32]))
    __shared__ __align__(16) float2 AV[WPB][Kx];   // (a_i, v_i)
    __shared__ unsigned char maskb[WPB][Tx];

    const int tid = threadIdx.x;
    const int w = tid >> 5;
    const int l = tid & 31;
    const int b = blockIdx.x * WPB + w;
    const bool active = (b < Bx);

    for (int idx = tid; idx < 32 * 32; idx += WPB * 32) {
        int i = (idx >> 5) + 32, c = idx & 31;
        float t0 = trans[i * Kx + c];
        float t1 = trans[i * Kx + c + 32];
        Tsm[idx] = make_float2(t0, t1);
        __nv_bfloat162 h = __float22bfloat162_rn(make_float2(__expf(t0), __expf(t1)));
        Esm[idx] = *reinterpret_cast<unsigned int*>(&h);
    }
    if (active) {
        for (int t = l; t < Tx; t += 32)
            maskb[w][t] = (unsigned char)(mask[b * Tx + t] != 0);
    }
    __syncthreads();
    if (!active) return;

    // registers: i in [0,32)
    float tr0[32], tr1[32];
    unsigned int ee[32];
    #pragma unroll
    for (int i = 0; i < 32; ++i) {
        tr0[i] = trans[i * Kx + l];
        tr1[i] = trans[i * Kx + l + 32];
        __nv_bfloat162 h = __float22bfloat162_rn(
            make_float2(__expf(tr0[i]), __expf(tr1[i])));
        ee[i] = *reinterpret_cast<unsigned int*>(&h);
    }

    const float* emp = em + (long)b * Tx * Kx;
    float2* vout = g_v + (long)b * 511 * 32 + l;

    float alpha0 = startt[l] + emp[l];
    float alpha1 = startt[l + 32] + emp[l + 32];
    float v0 = alpha0, v1 = alpha1;

    vout[0] = make_float2(v0, v1);   // row t=0

    for (int t = 1; t < Tx; ++t) {
        const float e0 = __ldg(emp + t * Kx + l);
        const float e1 = __ldg(emp + t * Kx + l + 32);
        const int mt = maskb[w][t];

        // m: any value near max works for exp stability (spread << 80)
        const float m = __shfl_sync(0xffffffffu, alpha0, 0);

        const float a0 = __expf(alpha0 - m);
        const float a1 = __expf(alpha1 - m);
        AV[w][l]      = make_float2(a0, v0);
        AV[w][l + 32] = make_float2(a1, v1);
        __syncwarp();

        // two independent chains (A: even offset, B: odd) per output for ILP
        float acc0A = 0.f, acc0B = 0.f, acc1A = 0.f, acc1B = 0.f;
        float b0A = NEG_INF, b0B = NEG_INF, b1A = NEG_INF, b1B = NEG_INF;

        // ---- i in [0,32): register-resident T/E ----
        #pragma unroll
        for (int ii = 0; ii < 16; ++ii) {
            const int i = 2 * ii;
            const float4 q = *(const float4*)(&AV[w][i]);   // a_i,v_i,a_{i+1},v_{i+1}
            {
                unsigned int ep = ee[i];
                float ef0 = __uint_as_float(ep << 16);
                float ef1 = __uint_as_float(ep & 0xffff0000u);
                acc0A += q.x * ef0;  acc1A += q.x * ef1;
                b0A = fmaxf(b0A, q.y + tr0[i]);
                b1A = fmaxf(b1A, q.y + tr1[i]);
            }
            {
                unsigned int ep = ee[i + 1];
                float ef0 = __uint_as_float(ep << 16);
                float ef1 = __uint_as_float(ep & 0xffff0000u);
                acc0B += q.z * ef0;  acc1B += q.z * ef1;
                b0B = fmaxf(b0B, q.w + tr0[i + 1]);
                b1B = fmaxf(b1B, q.w + tr1[i + 1]);
            }
        }
        // ---- i in [32,64): smem-resident T/E ----
        #pragma unroll
        for (int ii = 0; ii < 16; ++ii) {
            const int is = 2 * ii;               // smem-local i
            const float4 q = *(const float4*)(&AV[w][32 + is]);
            {
                float2 tp = Tsm[is * 32 + l];
                unsigned int ep = Esm[is * 32 + l];
                float ef0 = __uint_as_float(ep << 16);
                float ef1 = __uint_as_float(ep & 0xffff0000u);
                acc0A += q.x * ef0;  acc1A += q.x * ef1;
                b0A = fmaxf(b0A, q.y + tp.x);
                b1A = fmaxf(b1A, q.y + tp.y);
            }
            {
                float2 tp = Tsm[(is + 1) * 32 + l];
                unsigned int ep = Esm[(is + 1) * 32 + l];
                float ef0 = __uint_as_float(ep << 16);
                float ef1 = __uint_as_float(ep & 0xffff0000u);
                acc0B += q.z * ef0;  acc1B += q.z * ef1;
                b0B = fmaxf(b0B, q.w + tp.x);
                b1B = fmaxf(b1B, q.w + tp.y);
            }
        }

        const float na0 = m + __logf(acc0A + acc0B) + e0;
        const float na1 = m + __logf(acc1A + acc1B) + e1;
        const float nv0 = fmaxf(b0A, b0B) + e0;
        const float nv1 = fmaxf(b1A, b1B) + e1;

        if (mt) { alpha0 = na0; alpha1 = na1; v0 = nv0; v1 = nv1; }

        if (t < 511) vout[t * 32] = make_float2(v0, v1);
    }

    // ---- logZ = logsumexp(alpha + end) ----
    const float x0 = alpha0 + endt[l];
    const float x1 = alpha1 + endt[l + 32];
    float mm = fmaxf(x0, x1);
    #pragma unroll
    for (int o = 16; o; o >>= 1)
        mm = fmaxf(mm, __shfl_xor_sync(0xffffffffu, mm, o));
    float s = __expf(x0 - mm) + __expf(x1 - mm);
    #pragma unroll
    for (int o = 16; o; o >>= 1)
        s += __shfl_xor_sync(0xffffffffu, s, o);
    const float logZ = mm + __logf(s);

    // ---- last tag: argmax(v + end), first-index tie-break ----
    AV[w][l].x      = v0 + endt[l];
    AV[w][l + 32].x = v1 + endt[l + 32];
    __syncwarp();
    if (l == 0) {
        float bb = AV[w][0].x; int aa = 0;
        for (int i = 1; i < Kx; ++i) {
            float x = AV[w][i].x;
            if (x > bb) { bb = x; aa = i; }
        }
        g_last[b] = aa;
        out[b] = logZ;
    }
}

#define BTW 8   // warps (batches) per backtrace block

__global__ __launch_bounds__(BTW * 32) void crf_backtrace(
    const float* __restrict__ em, const int* __restrict__ tags,
    const int* __restrict__ mask, const float* __restrict__ trans,
    const float* __restrict__ startt, const float* __restrict__ endt,
    float* __restrict__ out)
{
    // Tt[c][l] = (T[l][c], T[l+32][c])  — transposed, paired
    __shared__ float2 Tt[Kx][32];
    __shared__ int path_s[BTW][Tx];
    __shared__ unsigned char mk[BTW][Tx];

    const int tid = threadIdx.x;
    const int w = tid >> 5;
    const int l = tid & 31;
    const int b = blockIdx.x * BTW + w;

    for (int idx = tid; idx < Kx * 32; idx += BTW * 32) {
        int c = idx >> 5, r = idx & 31;
        Tt[c][r] = make_float2(trans[r * Kx + c], trans[(r + 32) * Kx + c]);
    }
    for (int t = l; t < Tx; t += 32)
        mk[w][t] = (unsigned char)(mask[b * Tx + t] != 0);
    __syncthreads();

    // ---- gold score (warp-parallel) ----
    float gp = 0.f; int cnt = 0;
    for (int t = l; t < Tx; t += 32) {
        int mkt = mk[w][t];
        float mf = (float)mkt;
        cnt += mkt;
        int tg = tags[b * Tx + t];
        gp += em[((long)b * Tx + t) * Kx + tg] * mf;
        if (t > 0)
            gp += trans[tags[b * Tx + t - 1] * Kx + tg] * mf;
    }
    #pragma unroll
    for (int o = 16; o; o >>= 1) {
        gp  += __shfl_xor_sync(0xffffffffu, gp, o);
        cnt += __shfl_xor_sync(0xffffffffu, cnt, o);
    }

    // ---- path recovery: argmax only along the path ----
    const float2* vrows = g_v + (long)b * 511 * 32 + l;
    int cur = g_last[b];
    path_s[w][Tx - 1] = cur;

    float2 vrow = vrows[(Tx - 2) * 32];   // row t-1 for t = 511
    for (int t = Tx - 1; t >= 1; --t) {
        float2 vnext = vrows[((t >= 2) ? (t - 2) : 0) * 32];   // prefetch
        if (mk[w][t]) {
            float2 tp = Tt[cur][l];
            float x0 = vrow.x + tp.x;   // state l
            float x1 = vrow.y + tp.y;   // state l+32
            float bv; int bi;
            if (x1 > x0) { bv = x1; bi = l + 32; } else { bv = x0; bi = l; }
            #pragma unroll
            for (int o = 16; o; o >>= 1) {
                float ov = __shfl_xor_sync(0xffffffffu, bv, o);
                int   oi = __shfl_xor_sync(0xffffffffu, bi, o);
                if (ov > bv || (ov == bv && oi < bi)) { bv = ov; bi = oi; }
            }
            cur = bi;
        }
        path_s[w][t - 1] = cur;
        vrow = vnext;
    }

    if (l == 0) {
        int tg0 = tags[b * Tx];
        int tgl = tags[b * Tx + cnt - 1];
        float gold = gp + startt[tg0] + endt[tgl];
        out[b] = out[b] - gold;   // nll = logZ - gold
    }
    __syncwarp();

    for (int t = l; t < Tx; t += 32)
        out[Bx + (long)b * Tx + t] = (float)path_s[w][t];
}

extern "C" void kernel_launch(void* const* d_in, const int* in_sizes, int n_in,
                              void* d_out, int out_size)
{
    const float* em     = (const float*)d_in[0];
    const int*   tags   = (const int*)d_in[1];
    const int*   mask   = (const int*)d_in[2];
    const float* trans  = (const float*)d_in[3];
    const float* startt = (const float*)d_in[4];
    const float* endt   = (const float*)d_in[5];
    float* out = (float*)d_out;

    crf_forward<<<GRID, WPB * 32>>>(em, mask, trans, startt, endt, out);
    crf_backtrace<<<Bx / BTW, BTW * 32>>>(em, tags, mask, trans, startt, endt, out);
}

// round 4
// speedup vs baseline: 1.5777x; 1.0787x over previous
#include <cuda_runtime.h>
#include <cuda_bf16.h>
#include <cstdint>

#define Bx 1024
#define Tx 512
#define Kx 64
#define WPB 7
#define GRID ((Bx + WPB - 1) / WPB)   // 147

// v rows: g_v[(b*511 + t)*32 + l] = (v_t[l], v_t[l+32]), t = 0..510
__device__ float2 g_v[(long)Bx * 511 * 32];
__device__ int g_last[Bx];

#define NEG_INF __int_as_float(0xff800000)

__global__ __launch_bounds__(WPB * 32, 1) void crf_forward(
    const float* __restrict__ em, const int* __restrict__ mask,
    const float* __restrict__ trans, const float* __restrict__ startt,
    const float* __restrict__ endt, float* __restrict__ out)
{
    // smem: i in [32,64) only (i in [0,32) lives in registers)
    __shared__ float2 Tsm[32 * 32];          // Tsm[(i-32)*32+l] = (T[i][l], T[i][l+32])
    __shared__ unsigned int Esm[32 * 32];    // bf16x2(exp(T[i][l]), exp(T[i][l+32]))
    __shared__ __align__(16) float2 AV[WPB][Kx];   // (a_i, v_i)
    __shared__ unsigned char maskb[WPB][Tx];

    const int tid = threadIdx.x;
    const int w = tid >> 5;
    const int l = tid & 31;
    const int b = blockIdx.x * WPB + w;
    const bool active = (b < Bx);

    for (int idx = tid; idx < 32 * 32; idx += WPB * 32) {
        int i = (idx >> 5) + 32, c = idx & 31;
        float t0 = trans[i * Kx + c];
        float t1 = trans[i * Kx + c + 32];
        Tsm[idx] = make_float2(t0, t1);
        __nv_bfloat162 h = __float22bfloat162_rn(make_float2(__expf(t0), __expf(t1)));
        Esm[idx] = *reinterpret_cast<unsigned int*>(&h);
    }
    if (active) {
        for (int t = l; t < Tx; t += 32)
            maskb[w][t] = (unsigned char)(mask[b * Tx + t] != 0);
    }
    __syncthreads();
    if (!active) return;

    // registers: i in [0,32)
    float tr0[32], tr1[32];
    unsigned int ee[32];
    #pragma unroll
    for (int i = 0; i < 32; ++i) {
        tr0[i] = trans[i * Kx + l];
        tr1[i] = trans[i * Kx + l + 32];
        __nv_bfloat162 h = __float22bfloat162_rn(
            make_float2(__expf(tr0[i]), __expf(tr1[i])));
        ee[i] = *reinterpret_cast<unsigned int*>(&h);
    }

    const float* emp = em + (long)b * Tx * Kx;
    float2* vout = g_v + (long)b * 511 * 32 + l;

    float alpha0 = startt[l] + emp[l];
    float alpha1 = startt[l + 32] + emp[l + 32];
    float v0 = alpha0, v1 = alpha1;

    vout[0] = make_float2(v0, v1);   // row t=0

    for (int t = 1; t < Tx; ++t) {
        const float e0 = __ldg(emp + t * Kx + l);
        const float e1 = __ldg(emp + t * Kx + l + 32);
        const int mt = maskb[w][t];

        // m: any value near max works for exp stability (spread << 80)
        const float m = __shfl_sync(0xffffffffu, alpha0, 0);

        const float a0 = __expf(alpha0 - m);
        const float a1 = __expf(alpha1 - m);
        AV[w][l]      = make_float2(a0, v0);
        AV[w][l + 32] = make_float2(a1, v1);
        __syncwarp();

        // two independent chains (A: even offset, B: odd) per output for ILP
        float acc0A = 0.f, acc0B = 0.f, acc1A = 0.f, acc1B = 0.f;
        float b0A = NEG_INF, b0B = NEG_INF, b1A = NEG_INF, b1B = NEG_INF;

        // ---- i in [0,32): register-resident T/E ----
        #pragma unroll
        for (int ii = 0; ii < 16; ++ii) {
            const int i = 2 * ii;
            const float4 q = *(const float4*)(&AV[w][i]);   // a_i,v_i,a_{i+1},v_{i+1}
            {
                unsigned int ep = ee[i];
                float ef0 = __uint_as_float(ep << 16);
                float ef1 = __uint_as_float(ep & 0xffff0000u);
                acc0A += q.x * ef0;  acc1A += q.x * ef1;
                b0A = fmaxf(b0A, q.y + tr0[i]);
                b1A = fmaxf(b1A, q.y + tr1[i]);
            }
            {
                unsigned int ep = ee[i + 1];
                float ef0 = __uint_as_float(ep << 16);
                float ef1 = __uint_as_float(ep & 0xffff0000u);
                acc0B += q.z * ef0;  acc1B += q.z * ef1;
                b0B = fmaxf(b0B, q.w + tr0[i + 1]);
                b1B = fmaxf(b1B, q.w + tr1[i + 1]);
            }
        }
        // ---- i in [32,64): smem-resident T/E ----
        #pragma unroll
        for (int ii = 0; ii < 16; ++ii) {
            const int is = 2 * ii;               // smem-local i
            const float4 q = *(const float4*)(&AV[w][32 + is]);
            {
                float2 tp = Tsm[is * 32 + l];
                unsigned int ep = Esm[is * 32 + l];
                float ef0 = __uint_as_float(ep << 16);
                float ef1 = __uint_as_float(ep & 0xffff0000u);
                acc0A += q.x * ef0;  acc1A += q.x * ef1;
                b0A = fmaxf(b0A, q.y + tp.x);
                b1A = fmaxf(b1A, q.y + tp.y);
            }
            {
                float2 tp = Tsm[(is + 1) * 32 + l];
                unsigned int ep = Esm[(is + 1) * 32 + l];
                float ef0 = __uint_as_float(ep << 16);
                float ef1 = __uint_as_float(ep & 0xffff0000u);
                acc0B += q.z * ef0;  acc1B += q.z * ef1;
                b0B = fmaxf(b0B, q.w + tp.x);
                b1B = fmaxf(b1B, q.w + tp.y);
            }
        }

        const float na0 = m + __logf(acc0A + acc0B) + e0;
        const float na1 = m + __logf(acc1A + acc1B) + e1;
        const float nv0 = fmaxf(b0A, b0B) + e0;
        const float nv1 = fmaxf(b1A, b1B) + e1;

        if (mt) { alpha0 = na0; alpha1 = na1; v0 = nv0; v1 = nv1; }

        if (t < 511) vout[t * 32] = make_float2(v0, v1);
    }

    // ---- logZ = logsumexp(alpha + end) ----
    const float x0 = alpha0 + endt[l];
    const float x1 = alpha1 + endt[l + 32];
    float mm = fmaxf(x0, x1);
    #pragma unroll
    for (int o = 16; o; o >>= 1)
        mm = fmaxf(mm, __shfl_xor_sync(0xffffffffu, mm, o));
    float s = __expf(x0 - mm) + __expf(x1 - mm);
    #pragma unroll
    for (int o = 16; o; o >>= 1)
        s += __shfl_xor_sync(0xffffffffu, s, o);
    const float logZ = mm + __logf(s);

    // ---- last tag: argmax(v + end), first-index tie-break ----
    AV[w][l].x      = v0 + endt[l];
    AV[w][l + 32].x = v1 + endt[l + 32];
    __syncwarp();
    if (l == 0) {
        float bb = AV[w][0].x; int aa = 0;
        for (int i = 1; i < Kx; ++i) {
            float x = AV[w][i].x;
            if (x > bb) { bb = x; aa = i; }
        }
        g_last[b] = aa;
        out[b] = logZ;
    }
}

// Monotone bijective float -> u32 key (total order identical to < on finite floats)
__device__ __forceinline__ unsigned int fkey(float f) {
    unsigned int u = __float_as_uint(f);
    return (u & 0x80000000u) ? ~u : (u | 0x80000000u);
}

#define BTW 8   // warps (batches) per backtrace block

__global__ __launch_bounds__(BTW * 32) void crf_backtrace(
    const float* __restrict__ em, const int* __restrict__ tags,
    const int* __restrict__ mask, const float* __restrict__ trans,
    const float* __restrict__ startt, const float* __restrict__ endt,
    float* __restrict__ out)
{
    // Tt[c][l] = (T[l][c], T[l+32][c])  — transposed, paired
    __shared__ float2 Tt[Kx][32];
    __shared__ int path_s[BTW][Tx];
    __shared__ unsigned char mk[BTW][Tx];

    const int tid = threadIdx.x;
    const int w = tid >> 5;
    const int l = tid & 31;
    const int b = blockIdx.x * BTW + w;

    for (int idx = tid; idx < Kx * 32; idx += BTW * 32) {
        int c = idx >> 5, r = idx & 31;
        Tt[c][r] = make_float2(trans[r * Kx + c], trans[(r + 32) * Kx + c]);
    }
    for (int t = l; t < Tx; t += 32)
        mk[w][t] = (unsigned char)(mask[b * Tx + t] != 0);
    __syncthreads();

    // ---- gold score (warp-parallel) ----
    float gp = 0.f; int cnt = 0;
    for (int t = l; t < Tx; t += 32) {
        int mkt = mk[w][t];
        float mf = (float)mkt;
        cnt += mkt;
        int tg = tags[b * Tx + t];
        gp += em[((long)b * Tx + t) * Kx + tg] * mf;
        if (t > 0)
            gp += trans[tags[b * Tx + t - 1] * Kx + tg] * mf;
    }
    #pragma unroll
    for (int o = 16; o; o >>= 1) {
        gp  += __shfl_xor_sync(0xffffffffu, gp, o);
        cnt += __shfl_xor_sync(0xffffffffu, cnt, o);
    }

    // ---- path recovery: single REDUX.MAX + ballot per step ----
    const float2* vrows = g_v + (long)b * 511 * 32 + l;
    int cur = g_last[b];
    path_s[w][Tx - 1] = cur;

    float2 vrow = vrows[(Tx - 2) * 32];   // row t-1 for t = 511
    for (int t = Tx - 1; t >= 1; --t) {
        float2 vnext = vrows[((t >= 2) ? (t - 2) : 0) * 32];   // prefetch
        if (mk[w][t]) {                    // warp-uniform branch
            float2 tp = Tt[cur][l];
            unsigned int k0 = fkey(vrow.x + tp.x);   // state l
            unsigned int k1 = fkey(vrow.y + tp.y);   // state l+32
            unsigned int km = __reduce_max_sync(0xffffffffu, k0 > k1 ? k0 : k1);
            unsigned int m0 = __ballot_sync(0xffffffffu, k0 == km);
            unsigned int m1 = __ballot_sync(0xffffffffu, k1 == km);
            cur = m0 ? (__ffs(m0) - 1) : (32 + __ffs(m1) - 1);
        }
        path_s[w][t - 1] = cur;
        vrow = vnext;
    }

    if (l == 0) {
        int tg0 = tags[b * Tx];
        int tgl = tags[b * Tx + cnt - 1];
        float gold = gp + startt[tg0] + endt[tgl];
        out[b] = out[b] - gold;   // nll = logZ - gold
    }
    __syncwarp();

    for (int t = l; t < Tx; t += 32)
        out[Bx + (long)b * Tx + t] = (float)path_s[w][t];
}

extern "C" void kernel_launch(void* const* d_in, const int* in_sizes, int n_in,
                              void* d_out, int out_size)
{
    const float* em     = (const float*)d_in[0];
    const int*   tags   = (const int*)d_in[1];
    const int*   mask   = (const int*)d_in[2];
    const float* trans  = (const float*)d_in[3];
    const float* startt = (const float*)d_in[4];
    const float* endt   = (const float*)d_in[5];
    float* out = (float*)d_out;

    crf_forward<<<GRID, WPB * 32>>>(em, mask, trans, startt, endt, out);
    crf_backtrace<<<Bx / BTW, BTW * 32>>>(em, tags, mask, trans, startt, endt, out);
}

// round 5
// speedup vs baseline: 1.8228x; 1.1554x over previous
#include <cuda_runtime.h>
#include <cuda_bf16.h>
#include <cstdint>

#define Bx 1024
#define Tx 512
#define Kx 64
#define WPB 7
#define GRID ((Bx + WPB - 1) / WPB)   // 147

// v rows: g_v[(b*511 + t)*32 + l] = (v_t[l], v_t[l+32]), t = 0..510
__device__ float2 g_v[(long)Bx * 511 * 32];
__device__ int g_last[Bx];

#define NEG_INF __int_as_float(0xff800000)

__global__ __launch_bounds__(WPB * 32, 1) void crf_forward(
    const float* __restrict__ em, const int* __restrict__ mask,
    const float* __restrict__ trans, const float* __restrict__ startt,
    const float* __restrict__ endt, float* __restrict__ out)
{
    // smem: i in [32,64) only (i in [0,32) lives in registers)
    __shared__ float2 Tsm[32 * 32];          // Tsm[(i-32)*32+l] = (T[i][l], T[i][l+32])
    __shared__ unsigned int Esm[32 * 32];    // bf16x2(exp(T[i][l]), exp(T[i][l+32]))
    __shared__ __align__(16) float2 AV[WPB][Kx];   // (a_i, v_i)
    __shared__ unsigned char maskb[WPB][Tx];

    const int tid = threadIdx.x;
    const int w = tid >> 5;
    const int l = tid & 31;
    const int b = blockIdx.x * WPB + w;
    const bool active = (b < Bx);

    for (int idx = tid; idx < 32 * 32; idx += WPB * 32) {
        int i = (idx >> 5) + 32, c = idx & 31;
        float t0 = trans[i * Kx + c];
        float t1 = trans[i * Kx + c + 32];
        Tsm[idx] = make_float2(t0, t1);
        __nv_bfloat162 h = __float22bfloat162_rn(make_float2(__expf(t0), __expf(t1)));
        Esm[idx] = *reinterpret_cast<unsigned int*>(&h);
    }
    if (active) {
        for (int t = l; t < Tx; t += 32)
            maskb[w][t] = (unsigned char)(mask[b * Tx + t] != 0);
    }
    __syncthreads();
    if (!active) return;

    // registers: i in [0,32)
    float tr0[32], tr1[32];
    unsigned int ee[32];
    #pragma unroll
    for (int i = 0; i < 32; ++i) {
        tr0[i] = trans[i * Kx + l];
        tr1[i] = trans[i * Kx + l + 32];
        __nv_bfloat162 h = __float22bfloat162_rn(
            make_float2(__expf(tr0[i]), __expf(tr1[i])));
        ee[i] = *reinterpret_cast<unsigned int*>(&h);
    }

    const float* emp = em + (long)b * Tx * Kx;
    float2* vout = g_v + (long)b * 511 * 32 + l;

    float alpha0 = startt[l] + emp[l];
    float alpha1 = startt[l + 32] + emp[l + 32];
    float v0 = alpha0, v1 = alpha1;

    vout[0] = make_float2(v0, v1);   // row t=0

    for (int t = 1; t < Tx; ++t) {
        const float e0 = __ldg(emp + t * Kx + l);
        const float e1 = __ldg(emp + t * Kx + l + 32);
        const int mt = maskb[w][t];

        // m: any value near max works for exp stability (spread << 80)
        const float m = __shfl_sync(0xffffffffu, alpha0, 0);

        const float a0 = __expf(alpha0 - m);
        const float a1 = __expf(alpha1 - m);
        AV[w][l]      = make_float2(a0, v0);
        AV[w][l + 32] = make_float2(a1, v1);
        __syncwarp();

        // two independent chains (A: even offset, B: odd) per output for ILP
        float acc0A = 0.f, acc0B = 0.f, acc1A = 0.f, acc1B = 0.f;
        float b0A = NEG_INF, b0B = NEG_INF, b1A = NEG_INF, b1B = NEG_INF;

        // ---- i in [0,32): register-resident T/E ----
        #pragma unroll
        for (int ii = 0; ii < 16; ++ii) {
            const int i = 2 * ii;
            const float4 q = *(const float4*)(&AV[w][i]);   // a_i,v_i,a_{i+1},v_{i+1}
            {
                unsigned int ep = ee[i];
                float ef0 = __uint_as_float(ep << 16);
                float ef1 = __uint_as_float(ep & 0xffff0000u);
                acc0A += q.x * ef0;  acc1A += q.x * ef1;
                b0A = fmaxf(b0A, q.y + tr0[i]);
                b1A = fmaxf(b1A, q.y + tr1[i]);
            }
            {
                unsigned int ep = ee[i + 1];
                float ef0 = __uint_as_float(ep << 16);
                float ef1 = __uint_as_float(ep & 0xffff0000u);
                acc0B += q.z * ef0;  acc1B += q.z * ef1;
                b0B = fmaxf(b0B, q.w + tr0[i + 1]);
                b1B = fmaxf(b1B, q.w + tr1[i + 1]);
            }
        }
        // ---- i in [32,64): smem-resident T/E ----
        #pragma unroll
        for (int ii = 0; ii < 16; ++ii) {
            const int is = 2 * ii;               // smem-local i
            const float4 q = *(const float4*)(&AV[w][32 + is]);
            {
                float2 tp = Tsm[is * 32 + l];
                unsigned int ep = Esm[is * 32 + l];
                float ef0 = __uint_as_float(ep << 16);
                float ef1 = __uint_as_float(ep & 0xffff0000u);
                acc0A += q.x * ef0;  acc1A += q.x * ef1;
                b0A = fmaxf(b0A, q.y + tp.x);
                b1A = fmaxf(b1A, q.y + tp.y);
            }
            {
                float2 tp = Tsm[(is + 1) * 32 + l];
                unsigned int ep = Esm[(is + 1) * 32 + l];
                float ef0 = __uint_as_float(ep << 16);
                float ef1 = __uint_as_float(ep & 0xffff0000u);
                acc0B += q.z * ef0;  acc1B += q.z * ef1;
                b0B = fmaxf(b0B, q.w + tp.x);
                b1B = fmaxf(b1B, q.w + tp.y);
            }
        }

        const float na0 = m + __logf(acc0A + acc0B) + e0;
        const float na1 = m + __logf(acc1A + acc1B) + e1;
        const float nv0 = fmaxf(b0A, b0B) + e0;
        const float nv1 = fmaxf(b1A, b1B) + e1;

        if (mt) { alpha0 = na0; alpha1 = na1; v0 = nv0; v1 = nv1; }

        if (t < 511) vout[t * 32] = make_float2(v0, v1);
    }

    // ---- logZ = logsumexp(alpha + end) ----
    const float x0 = alpha0 + endt[l];
    const float x1 = alpha1 + endt[l + 32];
    float mm = fmaxf(x0, x1);
    #pragma unroll
    for (int o = 16; o; o >>= 1)
        mm = fmaxf(mm, __shfl_xor_sync(0xffffffffu, mm, o));
    float s = __expf(x0 - mm) + __expf(x1 - mm);
    #pragma unroll
    for (int o = 16; o; o >>= 1)
        s += __shfl_xor_sync(0xffffffffu, s, o);
    const float logZ = mm + __logf(s);

    // ---- last tag: argmax(v + end), first-index tie-break ----
    AV[w][l].x      = v0 + endt[l];
    AV[w][l + 32].x = v1 + endt[l + 32];
    __syncwarp();
    if (l == 0) {
        float bb = AV[w][0].x; int aa = 0;
        for (int i = 1; i < Kx; ++i) {
            float x = AV[w][i].x;
            if (x > bb) { bb = x; aa = i; }
        }
        g_last[b] = aa;
        out[b] = logZ;
    }
}

// Monotone bijective float -> u32 key (total order identical to < on finite floats)
__device__ __forceinline__ unsigned int fkey(float f) {
    unsigned int u = __float_as_uint(f);
    return (u & 0x80000000u) ? ~u : (u | 0x80000000u);
}

#define BTW 8   // warps (batches) per backtrace block

__global__ __launch_bounds__(BTW * 32) void crf_backtrace(
    const float* __restrict__ em, const int* __restrict__ tags,
    const int* __restrict__ mask, const float* __restrict__ trans,
    const float* __restrict__ startt, const float* __restrict__ endt,
    float* __restrict__ out)
{
    // Tt[c][l] = (T[l][c], T[l+32][c])  — transposed, paired
    __shared__ float2 Tt[Kx][32];
    __shared__ int path_s[BTW][Tx];
    __shared__ unsigned char mk[BTW][Tx];

    const int tid = threadIdx.x;
    const int w = tid >> 5;
    const int l = tid & 31;
    const int b = blockIdx.x * BTW + w;

    for (int idx = tid; idx < Kx * 32; idx += BTW * 32) {
        int c = idx >> 5, r = idx & 31;
        Tt[c][r] = make_float2(trans[r * Kx + c], trans[(r + 32) * Kx + c]);
    }
    for (int t = l; t < Tx; t += 32)
        mk[w][t] = (unsigned char)(mask[b * Tx + t] != 0);
    __syncthreads();

    // ---- gold score (warp-parallel) ----
    float gp = 0.f; int cnt = 0;
    for (int t = l; t < Tx; t += 32) {
        int mkt = mk[w][t];
        float mf = (float)mkt;
        cnt += mkt;
        int tg = tags[b * Tx + t];
        gp += em[((long)b * Tx + t) * Kx + tg] * mf;
        if (t > 0)
            gp += trans[tags[b * Tx + t - 1] * Kx + tg] * mf;
    }
    #pragma unroll
    for (int o = 16; o; o >>= 1) {
        gp  += __shfl_xor_sync(0xffffffffu, gp, o);
        cnt += __shfl_xor_sync(0xffffffffu, cnt, o);
    }
    if (l == 0) {
        int tg0 = tags[b * Tx];
        int tgl = tags[b * Tx + cnt - 1];
        float gold = gp + startt[tg0] + endt[tgl];
        out[b] = out[b] - gold;   // nll = logZ - gold
    }

    // ---- path recovery: deep-prefetched v rows + REDUX argmax ----
    // step s = 0..510 corresponds to t = 511-s; consumes v row r = 510-s.
    const float2* vrows = g_v + (long)b * 511 * 32 + l;
    int cur = g_last[b];
    path_s[w][Tx - 1] = cur;

    float2 ring[8];
    #pragma unroll
    for (int k = 0; k < 8; ++k)
        ring[k] = __ldg(vrows + (510 - k) * 32);

    #define BT_STEP(S, VR)                                                   \
    {                                                                        \
        const int t_ = 511 - (S);                                            \
        if (mk[w][t_]) {                                                     \
            float2 tp = Tt[cur][l];                                          \
            unsigned int k0 = fkey((VR).x + tp.x);                           \
            unsigned int k1 = fkey((VR).y + tp.y);                           \
            unsigned int km = __reduce_max_sync(0xffffffffu,                 \
                                                k0 > k1 ? k0 : k1);          \
            unsigned int m0 = __ballot_sync(0xffffffffu, k0 == km);          \
            unsigned int m1 = __ballot_sync(0xffffffffu, k1 == km);          \
            cur = m0 ? (__ffs(m0) - 1) : (32 + __ffs(m1) - 1);               \
        }                                                                    \
        path_s[w][t_ - 1] = cur;                                             \
    }

    for (int s0 = 0; s0 < 504; s0 += 8) {
        #pragma unroll
        for (int k = 0; k < 8; ++k) {
            const int s = s0 + k;
            const float2 vr = ring[k];
            const int rp = 510 - (s + 8);           // row for step s+8
            ring[k] = __ldg(vrows + (rp >= 0 ? rp : 0) * 32);
            BT_STEP(s, vr);
        }
    }
    #pragma unroll
    for (int k = 0; k < 7; ++k) {
        const int s = 504 + k;
        const float2 vr = ring[k];
        BT_STEP(s, vr);
    }
    #undef BT_STEP

    __syncwarp();
    for (int t = l; t < Tx; t += 32)
        out[Bx + (long)b * Tx + t] = (float)path_s[w][t];
}

extern "C" void kernel_launch(void* const* d_in, const int* in_sizes, int n_in,
                              void* d_out, int out_size)
{
    const float* em     = (const float*)d_in[0];
    const int*   tags   = (const int*)d_in[1];
    const int*   mask   = (const int*)d_in[2];
    const float* trans  = (const float*)d_in[3];
    const float* startt = (const float*)d_in[4];
    const float* endt   = (const float*)d_in[5];
    float* out = (float*)d_out;

    crf_forward<<<GRID, WPB * 32>>>(em, mask, trans, startt, endt, out);
    crf_backtrace<<<Bx / BTW, BTW * 32>>>(em, tags, mask, trans, startt, endt, out);
}